// round 12
// baseline (speedup 1.0000x reference)
#include <cuda_runtime.h>
#include <cuda_fp16.h>
#include <cuda_bf16.h>
#include <cstddef>
#include <cstdint>

// Problem constants (CTCLoss_56298431315981): T=1024, B=32, C=1024, L=128
constexpr int kT = 1024;
constexpr int kB = 32;
constexpr int kC = 1024;
constexpr int kL = 128;
constexpr int kS = 2 * kL + 1;   // 257 extended states
constexpr int kRowH = 256;       // halves per (b,t) row: 32 lanes x 8 fp16
constexpr int kTP = kT + 16;

// Scratch (static __device__ — no allocations allowed)
// Row layout (uint4 per lane): halves {p(5l),p(5l+1),p(5l+2),p(5l+3),p(5l+4),
// blank, 0, 0}; row-max normalized, p(k)=0 for k>=128.
__device__ __half g_E16[(size_t)kB * kTP * kRowH];
__device__ float  g_LG[kB * kTP];   // log2(rowmax) per (b,t), fp32 exact
__device__ float  g_nll[kB];

// ---------------------------------------------------------------------------
// 2^d as a product of two representable fp32 powers of two. Split factors are
// load-bearing: product can be inf, and 0*f1*f2 must stay 0 for empty halos.
// ---------------------------------------------------------------------------
__device__ __forceinline__ void twoFactor(int d, float& f1, float& f2)
{
    d = max(min(d, 252), -300);
    if (d < -252) { f1 = 0.f; f2 = 0.f; return; }
    const int dh = d / 2;
    f1 = __int_as_float((dh + 127) << 23);
    f2 = __int_as_float((d - dh + 127) << 23);
}

__device__ __forceinline__ unsigned h2u(__half2 h)
{
    return *reinterpret_cast<unsigned*>(&h);
}
__device__ __forceinline__ float2 u2f(unsigned u)
{
    return __half22float2(*reinterpret_cast<__half2*>(&u));
}

// ---------------------------------------------------------------------------
// Kernel 1: per-(t,b) softmax; row-max-normalized fp16 probs in DP-native
// packed layout + fp32 log2(rowmax) side array. MIDDLE-OUT t order so both DP
// warps (forward from 0, backward from Tb-1) start on L2-hot rows.
// ---------------------------------------------------------------------------
__global__ void __launch_bounds__(256) ctc_emis_kernel(
    const float* __restrict__ data, const int* __restrict__ labels)
{
    __shared__ float sh[8][kC];
    __shared__ int   shlab[8][kL];
    const int warp = threadIdx.x >> 5;
    const int lane = threadIdx.x & 31;
    const int g    = (blockIdx.x << 3) + warp;   // 0 .. T*B-1
    const int b    = g & 31;
    const int tlin = g >> 5;
    const int jj   = tlin >> 1;
    const int t    = (tlin & 1) ? (512 + jj) : (511 - jj);   // middle-out

    reinterpret_cast<int4*>(shlab[warp])[lane] =
        reinterpret_cast<const int4*>(labels + b * kL)[lane];

    const float4* src = reinterpret_cast<const float4*>(data + (size_t)(t * kB + b) * kC);

    float m = -3.4e38f;
    float4 v[8];
#pragma unroll
    for (int i = 0; i < 8; i++) {
        v[i] = src[(i << 5) + lane];
        reinterpret_cast<float4*>(sh[warp])[(i << 5) + lane] = v[i];
        m = fmaxf(m, fmaxf(fmaxf(v[i].x, v[i].y), fmaxf(v[i].z, v[i].w)));
    }
#pragma unroll
    for (int o = 16; o; o >>= 1) m = fmaxf(m, __shfl_xor_sync(0xffffffffu, m, o));

    float ssum = 0.f;
#pragma unroll
    for (int i = 0; i < 8; i++) {
        ssum += __expf(v[i].x - m) + __expf(v[i].y - m) +
                __expf(v[i].z - m) + __expf(v[i].w - m);
    }
#pragma unroll
    for (int o = 16; o; o >>= 1) ssum += __shfl_xor_sync(0xffffffffu, ssum, o);

    const float lse = m + __logf(ssum);

    __syncwarp();

    const float blank = __expf(sh[warp][0] - lse);
    float p[5];
#pragma unroll
    for (int j = 0; j < 5; j++) {
        const int idx = 5 * lane + j;
        p[j] = (idx < kL) ? __expf(sh[warp][shlab[warp][idx]] - lse) : 0.f;
    }

    float pmax = fmaxf(fmaxf(fmaxf(p[0], p[1]), fmaxf(p[2], p[3])),
                       fmaxf(p[4], blank));
#pragma unroll
    for (int o = 16; o; o >>= 1) pmax = fmaxf(pmax, __shfl_xor_sync(0xffffffffu, pmax, o));

    const float r   = __frcp_rn(pmax);
    const float lg2 = -__log2f(r);

    const __half2 q0 = __floats2half2_rn(p[0] * r, p[1] * r);
    const __half2 q1 = __floats2half2_rn(p[2] * r, p[3] * r);
    const __half2 q2 = __floats2half2_rn(p[4] * r, blank * r);

    uint4* dst = reinterpret_cast<uint4*>(g_E16 + ((size_t)b * kTP + t) * kRowH);
    dst[lane] = make_uint4(h2u(q0), h2u(q1), h2u(q2), 0u);
    if (lane == 0) g_LG[b * kTP + t] = lg2;
}

// ---------------------------------------------------------------------------
// Kernel 2: CTC forward+backward meet-in-the-middle. One CTA / batch element,
// 2 warps: warp 0 runs alpha for t=0..m, warp 1 runs beta for t=Tb-1..m
// (m = (Tb-1)/2). Pair-aligned states (lane l owns 10l..10l+9), linear
// domain, per-lane block floating point with 2-lane frame cap, rescale every
// 6 steps, 12-deep single-LDG fp16 ring. L = sum_s alpha_m(s)*beta_m(s).
// ---------------------------------------------------------------------------
__global__ void __launch_bounds__(64) ctc_dp_kernel(
    const int* __restrict__ labels, const int* __restrict__ llen,
    const int* __restrict__ dlen)
{
    __shared__ float AFs[320], BBs[320];
    __shared__ int   XFs[32],  XBs[32];

    const unsigned FULL = 0xffffffffu;
    const int NEGI = -(1 << 28);
    const int b    = blockIdx.x;
    const int lane = threadIdx.x & 31;
    const int w    = threadIdx.x >> 5;

    const int len = llen[b];
    const int Tb  = dlen[b];               // 512..1024
    const int mid = (Tb - 1) >> 1;         // meeting time (>=255)
    const __half* __restrict__ Eb = g_E16 + (size_t)b * kTP * kRowH;
    const int* __restrict__ lab   = labels + b * kL;

    if (w == 0) {
        // ===================== FORWARD (alpha), t = 0..mid ==================
        float allow[5];
#pragma unroll
        for (int k = 0; k < 5; k++) {
            const int li = 5 * lane + k;
            bool al = false;
            if (li >= 1 && li < kL) al = (lab[li] != lab[li - 1]);
            allow[k] = al ? 1.0f : 0.0f;
        }

        float a[10];
#pragma unroll
        for (int j = 0; j < 10; j++) a[j] = 0.f;
        if (lane == 0) {
            const uint4 r0 = __ldg(reinterpret_cast<const uint4*>(Eb));
            const float2 f0 = u2f(r0.x);          // p0, p1
            const float2 f2 = u2f(r0.z);          // p4, blank
            a[0] = f2.y;                          // t=0 state 0: blank
            a[1] = f0.x;                          // t=0 state 1: label 0
        }
        int   X   = 0;
        float sD1 = (lane == 0) ? 0.f : 1.f;
        float sD2 = (lane == 0) ? 0.f : 1.f;

        uint4 P[12];
#pragma unroll
        for (int q = 0; q < 12; q++)
            P[q] = __ldg(reinterpret_cast<const uint4*>(Eb + (size_t)(1 + q) * kRowH) + lane);

        auto dostep = [&](const uint4 Pq) {
            float h1 = __shfl_up_sync(FULL, a[9], 1);
            h1 = (h1 * sD1) * sD2;
            const float2 f0 = u2f(Pq.x);   // p(5l),  p(5l+1)
            const float2 f1 = u2f(Pq.y);   // p(5l+2),p(5l+3)
            const float2 f2 = u2f(Pq.z);   // p(5l+4),blank
            const float bl = f2.y;
            float na[10];
            na[0] = (a[0] + h1) * bl;
            na[1] = fmaf(allow[0], h1,   a[1] + a[0]) * f0.x;
            na[2] = (a[2] + a[1]) * bl;
            na[3] = fmaf(allow[1], a[1], a[3] + a[2]) * f0.y;
            na[4] = (a[4] + a[3]) * bl;
            na[5] = fmaf(allow[2], a[3], a[5] + a[4]) * f1.x;
            na[6] = (a[6] + a[5]) * bl;
            na[7] = fmaf(allow[3], a[5], a[7] + a[6]) * f1.y;
            na[8] = (a[8] + a[7]) * bl;
            na[9] = fmaf(allow[4], a[7], a[9] + a[8]) * f2.x;
#pragma unroll
            for (int j = 0; j < 10; j++) a[j] = na[j];
        };
        auto pref = [&](uint4& Pq, int trow) {
            Pq = __ldg(reinterpret_cast<const uint4*>(Eb + (size_t)trow * kRowH) + lane);
        };
        auto rescale = [&]() {
            float mm = a[0];
#pragma unroll
            for (int j = 1; j < 10; j++) mm = fmaxf(mm, a[j]);
            const bool nz = (mm > 0.f);
            const int  e    = nz ? (((__float_as_int(mm) >> 23) & 0xff) - 127) : 0;
            const int  cand = nz ? (X + e) : NEGI;
            const int  c1 = __shfl_up_sync(FULL, cand, 1);
            const int  c2 = __shfl_up_sync(FULL, cand, 2);
            int Xn;
            if (lane == 0) {
                Xn = nz ? cand : X;
            } else {
                const int low  = max(c1 - 24, c2 - 48);
                const int ownc = nz ? cand : NEGI;
                Xn = max(ownc, low);
                if (Xn <= NEGI) Xn = X;
            }
            float f1, f2;
            twoFactor(X - Xn, f1, f2);
#pragma unroll
            for (int j = 0; j < 10; j++) a[j] = (a[j] * f1) * f2;
            X = Xn;
            const int Xp = __shfl_up_sync(FULL, X, 1);
            twoFactor(Xp - X, sD1, sD2);
            if (lane == 0) { sD1 = 0.f; sD2 = 0.f; }
        };

        int t = 1;
        for (; t + 11 <= mid; t += 12) {
            dostep(P[0]);  pref(P[0],  t + 12);
            dostep(P[1]);  pref(P[1],  t + 13);
            dostep(P[2]);  pref(P[2],  t + 14);
            dostep(P[3]);  pref(P[3],  t + 15);
            dostep(P[4]);  pref(P[4],  t + 16);
            dostep(P[5]);  pref(P[5],  t + 17);
            rescale();
            dostep(P[6]);  pref(P[6],  t + 18);
            dostep(P[7]);  pref(P[7],  t + 19);
            dostep(P[8]);  pref(P[8],  t + 20);
            dostep(P[9]);  pref(P[9],  t + 21);
            dostep(P[10]); pref(P[10], t + 22);
            dostep(P[11]); pref(P[11], t + 23);
            rescale();
        }
        if (t <= mid) { dostep(P[0]); ++t; }
        if (t <= mid) { dostep(P[1]); ++t; }
        if (t <= mid) { dostep(P[2]); ++t; }
        if (t <= mid) { dostep(P[3]); ++t; }
        rescale();
        if (t <= mid) { dostep(P[4]); ++t; }
        if (t <= mid) { dostep(P[5]); ++t; }
        if (t <= mid) { dostep(P[6]); ++t; }
        if (t <= mid) { dostep(P[7]); ++t; }
        rescale();
        if (t <= mid) { dostep(P[8]); ++t; }
        if (t <= mid) { dostep(P[9]); ++t; }
        if (t <= mid) { dostep(P[10]); ++t; }

#pragma unroll
        for (int j = 0; j < 10; j++) AFs[10 * lane + j] = a[j];
        XFs[lane] = X;
    } else {
        // ===================== BACKWARD (beta), t = Tb-1..mid ===============
        float allowB[5];
#pragma unroll
        for (int k = 0; k < 5; k++) {
            const int li = 5 * lane + k + 1;
            bool al = false;
            if (li < kL) al = (lab[li] != lab[li - 1]);
            allowB[k] = al ? 1.0f : 0.0f;
        }

        const int sBl = 2 * len, sLl = sBl - 1;
        float bv[10];
#pragma unroll
        for (int j = 0; j < 10; j++) {
            const int s = 10 * lane + j;
            bv[j] = (s == sBl || s == sLl) ? 1.f : 0.f;
        }
        int   X   = 0;
        float sB1 = (lane == 31) ? 0.f : 1.f;
        float sB2 = (lane == 31) ? 0.f : 1.f;

        int tc = Tb - 2;
        uint4 P[12];
#pragma unroll
        for (int q = 0; q < 12; q++)
            P[q] = __ldg(reinterpret_cast<const uint4*>(Eb + (size_t)(Tb - 1 - q) * kRowH) + lane);

        auto dostepB = [&](const uint4 Pq) {
            const float2 f0 = u2f(Pq.x);
            const float2 f1 = u2f(Pq.y);
            const float2 f2 = u2f(Pq.z);
            const float bl = f2.y;
            float c[10];
            c[0] = bv[0] * bl;  c[1] = bv[1] * f0.x;
            c[2] = bv[2] * bl;  c[3] = bv[3] * f0.y;
            c[4] = bv[4] * bl;  c[5] = bv[5] * f1.x;
            c[6] = bv[6] * bl;  c[7] = bv[7] * f1.y;
            c[8] = bv[8] * bl;  c[9] = bv[9] * f2.x;
            float h0 = __shfl_down_sync(FULL, c[0], 1);
            float h1 = __shfl_down_sync(FULL, c[1], 1);
            h0 = (h0 * sB1) * sB2;
            h1 = (h1 * sB1) * sB2;
            float nb[10];
            nb[0] = c[0] + c[1];
            nb[1] = fmaf(allowB[0], c[3], c[1] + c[2]);
            nb[2] = c[2] + c[3];
            nb[3] = fmaf(allowB[1], c[5], c[3] + c[4]);
            nb[4] = c[4] + c[5];
            nb[5] = fmaf(allowB[2], c[7], c[5] + c[6]);
            nb[6] = c[6] + c[7];
            nb[7] = fmaf(allowB[3], c[9], c[7] + c[8]);
            nb[8] = c[8] + c[9];
            nb[9] = fmaf(allowB[4], h1,   c[9] + h0);
#pragma unroll
            for (int j = 0; j < 10; j++) bv[j] = nb[j];
            --tc;
        };
        auto prefB = [&](uint4& Pq, int trow) {
            Pq = __ldg(reinterpret_cast<const uint4*>(Eb + (size_t)trow * kRowH) + lane);
        };
        auto rescaleB = [&]() {
            float mm = bv[0];
#pragma unroll
            for (int j = 1; j < 10; j++) mm = fmaxf(mm, bv[j]);
            const bool nz = (mm > 0.f);
            const int  e    = nz ? (((__float_as_int(mm) >> 23) & 0xff) - 127) : 0;
            const int  cand = nz ? (X + e) : NEGI;
            const int  c1 = __shfl_down_sync(FULL, cand, 1);
            const int  c2 = __shfl_down_sync(FULL, cand, 2);
            int Xn;
            if (lane == 31) {
                Xn = nz ? cand : X;
            } else {
                const int low  = max(c1 - 24, c2 - 48);
                const int ownc = nz ? cand : NEGI;
                Xn = max(ownc, low);
                if (Xn <= NEGI) Xn = X;
            }
            float f1, f2;
            twoFactor(X - Xn, f1, f2);
#pragma unroll
            for (int j = 0; j < 10; j++) bv[j] = (bv[j] * f1) * f2;
            X = Xn;
            const int Xp = __shfl_down_sync(FULL, X, 1);
            twoFactor(Xp - X, sB1, sB2);
            if (lane == 31) { sB1 = 0.f; sB2 = 0.f; }
        };

        int rem = Tb - 1 - mid;
        for (; rem >= 12; rem -= 12) {
            dostepB(P[0]);  prefB(P[0],  tc - 10);
            dostepB(P[1]);  prefB(P[1],  tc - 10);
            dostepB(P[2]);  prefB(P[2],  tc - 10);
            dostepB(P[3]);  prefB(P[3],  tc - 10);
            dostepB(P[4]);  prefB(P[4],  tc - 10);
            dostepB(P[5]);  prefB(P[5],  tc - 10);
            rescaleB();
            dostepB(P[6]);  prefB(P[6],  tc - 10);
            dostepB(P[7]);  prefB(P[7],  tc - 10);
            dostepB(P[8]);  prefB(P[8],  tc - 10);
            dostepB(P[9]);  prefB(P[9],  tc - 10);
            dostepB(P[10]); prefB(P[10], tc - 10);
            dostepB(P[11]); prefB(P[11], tc - 10);
            rescaleB();
        }
        if (rem > 0) { dostepB(P[0]); --rem; }
        if (rem > 0) { dostepB(P[1]); --rem; }
        if (rem > 0) { dostepB(P[2]); --rem; }
        if (rem > 0) { dostepB(P[3]); --rem; }
        rescaleB();
        if (rem > 0) { dostepB(P[4]); --rem; }
        if (rem > 0) { dostepB(P[5]); --rem; }
        if (rem > 0) { dostepB(P[6]); --rem; }
        if (rem > 0) { dostepB(P[7]); --rem; }
        rescaleB();
        if (rem > 0) { dostepB(P[8]); --rem; }
        if (rem > 0) { dostepB(P[9]); --rem; }
        if (rem > 0) { dostepB(P[10]); --rem; }

#pragma unroll
        for (int j = 0; j < 10; j++) BBs[10 * lane + j] = bv[j];
        XBs[lane] = X;
    }

    __syncthreads();

    // ===== Combine: log2 L = LSE_s [log2 aF + XF + log2 bB + XB] + sum lgmax
    if (w == 0) {
        // exact fp32 sum of per-row log2(rowmax) over t in [0, Tb)
        float lg = 0.f;
        const float* LGb = g_LG + b * kTP;
        for (int i = lane; i < Tb; i += 32) lg += __ldg(LGb + i);
#pragma unroll
        for (int o = 16; o; o >>= 1) lg += __shfl_xor_sync(FULL, lg, o);

        float ys[9];
        float ymax = -1e30f;
#pragma unroll
        for (int k = 0; k < 9; k++) {
            const int s = lane + 32 * k;
            float y = -1e30f;
            if (s < kS) {
                const float af = AFs[s], bb = BBs[s];
                if (af > 0.f && bb > 0.f)
                    y = log2f(af) + log2f(bb) + (float)(XFs[s / 10] + XBs[s / 10]);
            }
            ys[k] = y;
            ymax = fmaxf(ymax, y);
        }
#pragma unroll
        for (int o = 16; o; o >>= 1) ymax = fmaxf(ymax, __shfl_xor_sync(FULL, ymax, o));
        float ssum = 0.f;
#pragma unroll
        for (int k = 0; k < 9; k++) ssum += exp2f(ys[k] - ymax);
#pragma unroll
        for (int o = 16; o; o >>= 1) ssum += __shfl_xor_sync(FULL, ssum, o);
        if (lane == 0) {
            const float rr = ymax + log2f(ssum) + lg;
            g_nll[b] = -rr * 0.69314718055994530942f;   // log2 -> ln
        }
    }
}

// ---------------------------------------------------------------------------
// Kernel 3: mean over batch -> d_out[0]. Deterministic (no atomics).
// ---------------------------------------------------------------------------
__global__ void ctc_finish_kernel(float* __restrict__ out)
{
    float v = g_nll[threadIdx.x];
#pragma unroll
    for (int o = 16; o; o >>= 1) v += __shfl_xor_sync(0xffffffffu, v, o);
    if (threadIdx.x == 0) out[0] = v * (1.0f / kB);
}

extern "C" void kernel_launch(void* const* d_in, const int* in_sizes, int n_in,
                              void* d_out, int out_size)
{
    const int*   labels       = (const int*)d_in[0];
    const float* data         = (const float*)d_in[1];
    const int*   label_length = (const int*)d_in[2];
    const int*   data_length  = (const int*)d_in[3];
    float*       out          = (float*)d_out;

    ctc_emis_kernel<<<(kT * kB) / 8, 256>>>(data, labels);
    ctc_dp_kernel<<<kB, 64>>>(labels, label_length, data_length);
    ctc_finish_kernel<<<1, 32>>>(out);
}